// round 1
// baseline (speedup 1.0000x reference)
#include <cuda_runtime.h>

// SSIM loss, separable Gaussian (11 taps), fused single-pass tile kernel.
// pred/target: [64,3,256,256] f32; window: [11,11] f32 = outer(g,g).
// out: scalar f32 = 1 - mean(ssim_map).

#define TW 32
#define TH 32
#define HALO 5
#define IN_W (TW + 2*HALO)      // 42
#define IN_H (TH + 2*HALO)      // 42
#define IN_STRIDE 48            // float2 row stride (pad for conflicts)
#define HC_STRIDE (TW + 1)      // 33
#define NTHREADS 256
#define IMG_H 256
#define IMG_W 256
#define NIMG 192                // 64 * 3
#define TILES_X (IMG_W / TW)    // 8
#define TILES_Y (IMG_H / TH)    // 8
#define NBLOCKS (NIMG * TILES_X * TILES_Y)  // 12288
#define NPIX ((long long)NIMG * IMG_H * IMG_W)

__device__ float g_partials[NBLOCKS];

__global__ __launch_bounds__(NTHREADS) void ssim_main_kernel(
    const float* __restrict__ pred,
    const float* __restrict__ target,
    const float* __restrict__ window)
{
    __shared__ float2 in_s[IN_H][IN_STRIDE];        // (pred, target) with halo
    __shared__ float  hc[5][IN_H * HC_STRIDE];      // h-convolved fields
    __shared__ float  warp_sums[NTHREADS / 32];

    const int tid = threadIdx.x;
    const int img = blockIdx.z;
    const int x0 = blockIdx.x * TW;
    const int y0 = blockIdx.y * TH;

    const float* p_base = pred   + (size_t)img * (IMG_H * IMG_W);
    const float* t_base = target + (size_t)img * (IMG_H * IMG_W);

    // Reconstruct separable 1D gaussian from the 2D window:
    // window[i][j] = g_i * g_j  =>  g_i = window[5][i] / sqrt(window[5][5])
    float g[11];
    {
        float inv = rsqrtf(window[5 * 11 + 5]);
        #pragma unroll
        for (int i = 0; i < 11; i++) g[i] = window[5 * 11 + i] * inv;
    }

    // ---- Load tile + halo (zero padding outside image) ----
    for (int idx = tid; idx < IN_H * IN_W; idx += NTHREADS) {
        int ly = idx / IN_W;
        int lx = idx - ly * IN_W;
        int gx = x0 + lx - HALO;
        int gy = y0 + ly - HALO;
        float p = 0.f, t = 0.f;
        if ((unsigned)gx < IMG_W && (unsigned)gy < IMG_H) {
            p = __ldg(p_base + gy * IMG_W + gx);
            t = __ldg(t_base + gy * IMG_W + gx);
        }
        in_s[ly][lx] = make_float2(p, t);
    }
    __syncthreads();

    // ---- Horizontal pass: 5 fields formed on the fly ----
    for (int idx = tid; idx < IN_H * TW; idx += NTHREADS) {
        int r = idx >> 5;        // / TW
        int c = idx & (TW - 1);  // % TW
        float a1 = 0.f, a2 = 0.f, a11 = 0.f, a22 = 0.f, a12 = 0.f;
        #pragma unroll
        for (int k = 0; k < 11; k++) {
            float2 v = in_s[r][c + k];
            float gk = g[k];
            a1  += gk * v.x;
            a2  += gk * v.y;
            a11 += gk * (v.x * v.x);
            a22 += gk * (v.y * v.y);
            a12 += gk * (v.x * v.y);
        }
        int o = r * HC_STRIDE + c;
        hc[0][o] = a1;
        hc[1][o] = a2;
        hc[2][o] = a11;
        hc[3][o] = a22;
        hc[4][o] = a12;
    }
    __syncthreads();

    // ---- Vertical pass + SSIM: each thread owns 4 consecutive output rows
    //      of one column; 14 row-loads feed 4 outputs (register sliding) ----
    const int c  = tid & (TW - 1);
    const int r0 = (tid >> 5) * 4;   // 8 warps * 4 rows = 32 rows

    float m1[4]  = {0.f, 0.f, 0.f, 0.f};
    float m2[4]  = {0.f, 0.f, 0.f, 0.f};
    float v11[4] = {0.f, 0.f, 0.f, 0.f};
    float v22[4] = {0.f, 0.f, 0.f, 0.f};
    float v12[4] = {0.f, 0.f, 0.f, 0.f};

    #pragma unroll
    for (int rr = 0; rr < 14; rr++) {
        int o = (r0 + rr) * HC_STRIDE + c;
        float h0 = hc[0][o];
        float h1 = hc[1][o];
        float h2 = hc[2][o];
        float h3 = hc[3][o];
        float h4 = hc[4][o];
        #pragma unroll
        for (int j = 0; j < 4; j++) {
            int k = rr - j;               // compile-time after unroll
            if (k >= 0 && k < 11) {
                float gk = g[k];
                m1[j]  += gk * h0;
                m2[j]  += gk * h1;
                v11[j] += gk * h2;
                v22[j] += gk * h3;
                v12[j] += gk * h4;
            }
        }
    }

    const float C1 = 1e-4f;   // 0.01^2
    const float C2 = 9e-4f;   // 0.03^2
    float local = 0.f;
    #pragma unroll
    for (int j = 0; j < 4; j++) {
        float mu1  = m1[j], mu2 = m2[j];
        float mu12 = mu1 * mu2;
        float mu1s = mu1 * mu1;
        float mu2s = mu2 * mu2;
        float num  = (2.f * mu12 + C1) * (2.f * (v12[j] - mu12) + C2);
        float den  = (mu1s + mu2s + C1) *
                     ((v11[j] - mu1s) + (v22[j] - mu2s) + C2);
        local += __fdividef(num, den);
    }

    // ---- Deterministic block reduction ----
    #pragma unroll
    for (int off = 16; off; off >>= 1)
        local += __shfl_down_sync(0xffffffffu, local, off);
    if ((tid & 31) == 0) warp_sums[tid >> 5] = local;
    __syncthreads();
    if (tid < 8) {
        float s = warp_sums[tid];
        #pragma unroll
        for (int off = 4; off; off >>= 1)
            s += __shfl_down_sync(0x000000ffu, s, off);
        if (tid == 0) {
            int bidx = (blockIdx.z * TILES_Y + blockIdx.y) * TILES_X + blockIdx.x;
            g_partials[bidx] = s;
        }
    }
}

__global__ __launch_bounds__(256) void ssim_finalize_kernel(float* __restrict__ out)
{
    __shared__ double warp_sums[8];
    const int tid = threadIdx.x;
    double s = 0.0;
    for (int i = tid; i < NBLOCKS; i += 256)
        s += (double)g_partials[i];
    #pragma unroll
    for (int off = 16; off; off >>= 1)
        s += __shfl_down_sync(0xffffffffu, s, off);
    if ((tid & 31) == 0) warp_sums[tid >> 5] = s;
    __syncthreads();
    if (tid < 8) {
        double t = warp_sums[tid];
        #pragma unroll
        for (int off = 4; off; off >>= 1)
            t += __shfl_down_sync(0x000000ffu, t, off);
        if (tid == 0)
            out[0] = (float)(1.0 - t / (double)NPIX);
    }
}

extern "C" void kernel_launch(void* const* d_in, const int* in_sizes, int n_in,
                              void* d_out, int out_size)
{
    (void)in_sizes; (void)n_in; (void)out_size;
    const float* pred   = (const float*)d_in[0];
    const float* target = (const float*)d_in[1];
    const float* window = (const float*)d_in[2];

    dim3 grid(TILES_X, TILES_Y, NIMG);
    ssim_main_kernel<<<grid, NTHREADS>>>(pred, target, window);
    ssim_finalize_kernel<<<1, 256>>>((float*)d_out);
}

// round 2
// speedup vs baseline: 1.0058x; 1.0058x over previous
#include <cuda_runtime.h>

// SSIM loss — separable 11-tap Gaussian, fused tile kernel, f32x2 packed FMA.
// pred/target: [64,3,256,256] f32; window = outer(g,g); out scalar f32.

#define TW 32
#define TH 64
#define HALO 5
#define IN_W 42          // TW + 10
#define IN_H 74          // TH + 10
#define PS 43            // p/t smem row stride (floats) — conflict-free for (r,q) map
#define IMG_H 256
#define IMG_W 256
#define NIMG 192
#define TX 8
#define TY 4
#define NBLOCKS (NIMG * TX * TY)   // 6144
#define NTHREADS 256
#define HTASKS (IN_H * 4)          // 296 (4 octets of 8 cols per row)

// dynamic smem layout (bytes):
//  p_s  : [0,            12728)   74*43 floats
//  t_s  : [12728,        25456)
//  hc4  : [25456,        63344)   74*32 ulonglong2 (float4), swizzled cols
//  hcE  : [63344,        73112)   74*33 floats
#define SMEM_TOTAL 73112

typedef unsigned long long u64;

__device__ __align__(16) float g_partials[NBLOCKS];

__device__ __forceinline__ u64 pack2(float x, float y) {
    u64 r; asm("mov.b64 %0, {%1,%2};" : "=l"(r) : "f"(x), "f"(y)); return r;
}
__device__ __forceinline__ float2 unpack2(u64 v) {
    float2 r; asm("mov.b64 {%0,%1}, %2;" : "=f"(r.x), "=f"(r.y) : "l"(v)); return r;
}
__device__ __forceinline__ void fma2(u64 &d, u64 a, u64 b) {
    asm("fma.rn.f32x2 %0, %1, %2, %0;" : "+l"(d) : "l"(a), "l"(b));
}
__device__ __forceinline__ u64 mul2(u64 a, u64 b) {
    u64 d; asm("mul.rn.f32x2 %0, %1, %2;" : "=l"(d) : "l"(a), "l"(b)); return d;
}

__global__ __launch_bounds__(NTHREADS) void ssim_main_kernel(
    const float* __restrict__ pred,
    const float* __restrict__ target,
    const float* __restrict__ window)
{
    extern __shared__ float smem_f[];
    float*      p_s = smem_f;
    float*      t_s = smem_f + IN_H * PS;
    ulonglong2* hc4 = (ulonglong2*)(smem_f + 2 * IN_H * PS);
    float*      hcE = (float*)((char*)smem_f + 63344);
    __shared__ float wsum[NTHREADS / 32];

    const int tid = threadIdx.x;
    const int img = blockIdx.z;
    const int x0 = blockIdx.x * TW;
    const int y0 = blockIdx.y * TH;

    const float* p_base = pred   + (size_t)img * (IMG_H * IMG_W);
    const float* t_base = target + (size_t)img * (IMG_H * IMG_W);

    // 1D gaussian from 2D window: g_i = w[5][i] * rsqrt(w[5][5])
    float gs[11];
    u64   gg[11];
    {
        float inv = rsqrtf(window[5 * 11 + 5]);
        #pragma unroll
        for (int i = 0; i < 11; i++) {
            gs[i] = window[5 * 11 + i] * inv;
            gg[i] = pack2(gs[i], gs[i]);
        }
    }

    // ---- Load tile + halo (zero pad) into separate p/t planes ----
    for (int idx = tid; idx < IN_H * IN_W; idx += NTHREADS) {
        int ly = idx / IN_W;
        int lx = idx - ly * IN_W;
        int gx = x0 + lx - HALO;
        int gy = y0 + ly - HALO;
        float p = 0.f, t = 0.f;
        if ((unsigned)gx < IMG_W && (unsigned)gy < IMG_H) {
            p = __ldg(p_base + gy * IMG_W + gx);
            t = __ldg(t_base + gy * IMG_W + gx);
        }
        p_s[ly * PS + lx] = p;
        t_s[ly * PS + lx] = t;
    }
    __syncthreads();

    // ---- Horizontal pass: register sliding, 8 outputs/task, packed FMA ----
    for (int task = tid; task < HTASKS; task += NTHREADS) {
        const int r  = task >> 2;
        const int c0 = (task & 3) * 8;
        const float* pr = p_s + r * PS + c0;
        const float* tr = t_s + r * PS + c0;

        u64 aA[8], aB[8];
        float aC[8];
        #pragma unroll
        for (int j = 0; j < 8; j++) { aA[j] = 0ull; aB[j] = 0ull; aC[j] = 0.f; }

        #pragma unroll
        for (int i = 0; i < 18; i++) {
            float p = pr[i];
            float t = tr[i];
            u64 v  = pack2(p, t);        // (p, t)
            u64 v2 = mul2(v, v);          // (p^2, t^2) — once per pixel
            float pt = p * t;
            #pragma unroll
            for (int j = 0; j < 8; j++) {
                int k = i - j;            // compile-time after unroll
                if (k >= 0 && k < 11) {
                    fma2(aA[j], gg[k], v);
                    fma2(aB[j], gg[k], v2);
                    aC[j] += gs[k] * pt;
                }
            }
        }

        const int s = r & 7;
        #pragma unroll
        for (int j = 0; j < 8; j++) {
            int csw = (c0 + j) ^ s;      // bank swizzle for 128-bit accesses
            hc4[r * 32 + csw] = make_ulonglong2(aA[j], aB[j]);
            hcE[r * 33 + c0 + j] = aC[j];
        }
    }
    __syncthreads();

    // ---- Vertical pass + SSIM: thread owns col c, 8 rows; 18 sliding loads ----
    const int c  = tid & 31;
    const int r0 = (tid >> 5) * 8;       // 8 warps * 8 rows = 64

    u64 aMu[8], aSg[8];
    float aPt[8];
    #pragma unroll
    for (int j = 0; j < 8; j++) { aMu[j] = 0ull; aSg[j] = 0ull; aPt[j] = 0.f; }

    #pragma unroll
    for (int rr = 0; rr < 18; rr++) {
        int ra = r0 + rr;
        ulonglong2 u = hc4[ra * 32 + (c ^ (ra & 7))];
        float hE = hcE[ra * 33 + c];
        #pragma unroll
        for (int j = 0; j < 8; j++) {
            int k = rr - j;
            if (k >= 0 && k < 11) {
                fma2(aMu[j], gg[k], u.x);   // (mu1, mu2)
                fma2(aSg[j], gg[k], u.y);   // (E[p^2], E[t^2])
                aPt[j] += gs[k] * hE;       // E[pt]
            }
        }
    }

    const float C1 = 1e-4f;
    const float C2 = 9e-4f;
    float local = 0.f;
    #pragma unroll
    for (int j = 0; j < 8; j++) {
        float2 mu = unpack2(aMu[j]);
        float2 sq = unpack2(aSg[j]);
        float mu12 = mu.x * mu.y;
        float mu1s = mu.x * mu.x;
        float mu2s = mu.y * mu.y;
        float num  = (2.f * mu12 + C1) * (2.f * (aPt[j] - mu12) + C2);
        float den  = (mu1s + mu2s + C1) *
                     ((sq.x - mu1s) + (sq.y - mu2s) + C2);
        local += __fdividef(num, den);
    }

    // ---- Deterministic block reduction ----
    #pragma unroll
    for (int off = 16; off; off >>= 1)
        local += __shfl_down_sync(0xffffffffu, local, off);
    if ((tid & 31) == 0) wsum[tid >> 5] = local;
    __syncthreads();
    if (tid < 8) {
        float v = wsum[tid];
        #pragma unroll
        for (int off = 4; off; off >>= 1)
            v += __shfl_down_sync(0x000000ffu, v, off);
        if (tid == 0) {
            int bidx = (blockIdx.z * TY + blockIdx.y) * TX + blockIdx.x;
            g_partials[bidx] = v;
        }
    }
}

__global__ __launch_bounds__(256) void ssim_finalize_kernel(float* __restrict__ out)
{
    __shared__ double warp_sums[8];
    const int tid = threadIdx.x;
    const float4* p4 = (const float4*)g_partials;
    double s = 0.0;
    #pragma unroll
    for (int i = 0; i < NBLOCKS / 4 / 256; i++) {
        float4 v = p4[tid + i * 256];
        s += (double)v.x + (double)v.y + (double)v.z + (double)v.w;
    }
    #pragma unroll
    for (int off = 16; off; off >>= 1)
        s += __shfl_down_sync(0xffffffffu, s, off);
    if ((tid & 31) == 0) warp_sums[tid >> 5] = s;
    __syncthreads();
    if (tid < 8) {
        double t = warp_sums[tid];
        #pragma unroll
        for (int off = 4; off; off >>= 1)
            t += __shfl_down_sync(0x000000ffu, t, off);
        if (tid == 0)
            out[0] = (float)(1.0 - t / ((double)NIMG * IMG_H * IMG_W));
    }
}

extern "C" void kernel_launch(void* const* d_in, const int* in_sizes, int n_in,
                              void* d_out, int out_size)
{
    (void)in_sizes; (void)n_in; (void)out_size;
    const float* pred   = (const float*)d_in[0];
    const float* target = (const float*)d_in[1];
    const float* window = (const float*)d_in[2];

    static int attr_set = 0;
    if (!attr_set) {
        cudaFuncSetAttribute(ssim_main_kernel,
                             cudaFuncAttributeMaxDynamicSharedMemorySize,
                             SMEM_TOTAL);
        attr_set = 1;
    }

    dim3 grid(TX, TY, NIMG);
    ssim_main_kernel<<<grid, NTHREADS, SMEM_TOTAL>>>(pred, target, window);
    ssim_finalize_kernel<<<1, 256>>>((float*)d_out);
}